// round 6
// baseline (speedup 1.0000x reference)
#include <cuda_runtime.h>
#include <cuda_bf16.h>
#include <cstdint>
#include <cstddef>

#define B_ 64
#define S_ 512
#define I_ 768
#define H_ 512
#define G_ 2048            // 4*H
#define M_ 32768           // B*S

// ---------------- device scratch (static: no allocations allowed) ----------------
// xp: gate-interleaved input projection  [dir][m][u*4+g], g in {i,f,g,o}
__device__ __align__(16) float g_xp[2][(size_t)M_ * G_];        // 512 MB
// Wh pre-interleaved: [dir][ub][k][u_off][g]  (ub = unit-block of 8 units)
__device__ __align__(16) float g_whx[2][64][512][8][4];         // 8 MB
// hidden state ping-pong: [parity][dir][b*512+u]
__device__ __align__(16) float g_h[2][2][B_ * H_];
// cell state: [dir][b*512+u]
__device__ __align__(16) float g_c[2][B_ * H_];

// ---------------- helpers ----------------
__device__ __forceinline__ unsigned long long splat2(float v) {
    unsigned long long r;
    asm("mov.b64 %0, {%1, %1};" : "=l"(r) : "f"(v));
    return r;
}
__device__ __forceinline__ void fma2(unsigned long long& acc,
                                     unsigned long long a, unsigned long long b) {
    asm("fma.rn.f32x2 %0, %1, %2, %0;" : "+l"(acc) : "l"(a), "l"(b));
}
__device__ __forceinline__ float sigmoidf_(float x) {
    return 1.0f / (1.0f + expf(-x));
}

// ---------------- prep: zero state + build interleaved Wh ----------------
__global__ void prep_kernel(const float* __restrict__ Wh_f,
                            const float* __restrict__ Wh_b) {
    int idx = blockIdx.x * blockDim.x + threadIdx.x;
    // whx: 2 * 512 * 2048 = 2,097,152 entries
    if (idx < 2 * H_ * G_) {
        int d = idx >> 20;                 // 64*512*8*4 = 2^20 per dir
        int r = idx & ((1 << 20) - 1);     // ((ub*512+k)*8+u_off)*4+g
        int g     = r & 3;
        int u_off = (r >> 2) & 7;
        int k     = (r >> 5) & 511;
        int ub    = r >> 14;
        const float* Wh = d ? Wh_b : Wh_f;
        ((float*)g_whx)[idx] = Wh[k * G_ + g * H_ + ub * 8 + u_off];
    }
    // zero h parity-0 (both dirs) and c (both dirs): 65536 each
    if (idx < 2 * B_ * H_) {
        ((float*)g_h)[idx] = 0.0f;   // g_h[0][*][*]
        ((float*)g_c)[idx] = 0.0f;
    }
}

// ---------------- projection GEMM: xp = x @ Wi + bi + bh (both dirs) ----------------
// Tile: BM=128, BN=128, BK=16, 256 threads, 8x8 per thread, f32x2 accumulation
// (pairs packed along M; As stored k-major so row pairs are contiguous).
#define BM 128
#define BN 128
#define BK 16

__global__ __launch_bounds__(256) void proj_kernel(
    const float* __restrict__ x,
    const float* __restrict__ Wi_f, const float* __restrict__ bi_f,
    const float* __restrict__ bh_f,
    const float* __restrict__ Wi_b, const float* __restrict__ bi_b,
    const float* __restrict__ bh_b)
{
    __shared__ float As[BK][BM];   // transposed: As[k][m]
    __shared__ float Bs[BK][BN];   // Bs[k][n]

    const int d  = blockIdx.z;
    const float* __restrict__ Wi = d ? Wi_b : Wi_f;
    const float* __restrict__ bi = d ? bi_b : bi_f;
    const float* __restrict__ bh = d ? bh_b : bh_f;

    const int mb = blockIdx.y;     // 0..255
    const int nb = blockIdx.x;     // 0..15
    const int tid = threadIdx.x;
    const int tx = tid & 15;       // n sub-tile: cols tx*8..+7
    const int ty = tid >> 4;       // m sub-tile: rows ty*8..+7 (4 f32x2 pairs)

    unsigned long long acc[4][8];
#pragma unroll
    for (int p = 0; p < 4; p++)
#pragma unroll
        for (int c = 0; c < 8; c++) acc[p][c] = 0ULL;

    const int arow  = tid >> 2;    // 0..63
    const int acol4 = tid & 3;     // 0..3
    const float* __restrict__ xg = x + (size_t)(mb * BM) * I_;
    const float* __restrict__ wg = Wi + (size_t)(nb * BN);

    for (int kc = 0; kc < I_; kc += BK) {
        // A tile: 128 rows x 16 k, transposed into As[k][m]
#pragma unroll
        for (int j = 0; j < 2; j++) {
            int r = arow + j * 64;
            float4 v = *(const float4*)(xg + (size_t)r * I_ + kc + acol4 * 4);
            As[acol4 * 4 + 0][r] = v.x;
            As[acol4 * 4 + 1][r] = v.y;
            As[acol4 * 4 + 2][r] = v.z;
            As[acol4 * 4 + 3][r] = v.w;
        }
        // B tile: 16 k x 128 cols, natural layout
#pragma unroll
        for (int j = 0; j < 2; j++) {
            int idx = j * 256 + tid;
            int r = idx >> 5, c4 = idx & 31;
            float4 v = *(const float4*)(wg + (size_t)(kc + r) * G_ + c4 * 4);
            *(float4*)&Bs[r][c4 * 4] = v;
        }
        __syncthreads();

#pragma unroll
        for (int k = 0; k < BK; k++) {
            unsigned long long a[4];
#pragma unroll
            for (int p = 0; p < 4; p++)
                a[p] = *(const unsigned long long*)&As[k][ty * 8 + 2 * p];
            float4 bv0 = *(const float4*)&Bs[k][tx * 8];
            float4 bv1 = *(const float4*)&Bs[k][tx * 8 + 4];
            float bcols[8] = {bv0.x, bv0.y, bv0.z, bv0.w,
                              bv1.x, bv1.y, bv1.z, bv1.w};
#pragma unroll
            for (int c = 0; c < 8; c++) {
                unsigned long long bs = splat2(bcols[c]);
#pragma unroll
                for (int p = 0; p < 4; p++) fma2(acc[p][c], a[p], bs);
            }
        }
        __syncthreads();
    }

    // Epilogue: add (bi+bh), write gate-interleaved xp[m][u*4+g]
    float* __restrict__ xpd = g_xp[d];
    const int m0 = mb * BM + ty * 8;
    const int n0 = nb * BN + tx * 8;
#pragma unroll
    for (int c = 0; c < 8; c++) {
        int col  = n0 + c;
        float bias = bi[col] + bh[col];
        int u = col & 511;
        int g = col >> 9;
        size_t off = (size_t)(u * 4 + g);
#pragma unroll
        for (int p = 0; p < 4; p++) {
            float2 v = *(float2*)&acc[p][c];   // lo = row m0+2p, hi = m0+2p+1
            xpd[(size_t)(m0 + 2 * p)     * G_ + off] = v.x + bias;
            xpd[(size_t)(m0 + 2 * p + 1) * G_ + off] = v.y + bias;
        }
    }
}

// ---------------- LSTM step: gates = xp[t] + h_prev @ Wh, then pointwise ----------------
// Grid: 128 blocks = 2 dirs x 64 unit-blocks (8 units each). 256 threads.
// smem: h_prev (64x512 = 128 KB) + Wh slice (512x8x4 = 64 KB) = 192 KB.
// Thread = (batch pair, one unit): 4 gate dot-products via gate-paired f32x2.
__global__ __launch_bounds__(256) void step_kernel(
    const float* __restrict__ sent, float* __restrict__ out, int s)
{
    extern __shared__ float sm[];
    float* h_sm = sm;                  // [b][k]  64*512
    float* w_sm = sm + B_ * H_;        // [k][u_off][g]  512*8*4

    const int blk = blockIdx.x;
    const int d  = blk >> 6;
    const int ub = blk & 63;
    const int t  = d ? (S_ - 1 - s) : s;
    const int p  = s & 1;
    const float* __restrict__ h_prev = g_h[p][d];
    float* __restrict__ h_next       = g_h[p ^ 1][d];
    const int tid = threadIdx.x;

    // stage h_prev: 8192 float4
    {
        const float4* hp4 = (const float4*)h_prev;
        float4* hs4 = (float4*)h_sm;
#pragma unroll
        for (int i = 0; i < 32; i++) hs4[i * 256 + tid] = hp4[i * 256 + tid];
    }
    // stage Wh slice (contiguous 64 KB): 4096 float4
    {
        const float4* wp4 = (const float4*)&g_whx[d][ub][0][0][0];
        float4* ws4 = (float4*)w_sm;
#pragma unroll
        for (int i = 0; i < 16; i++) ws4[i * 256 + tid] = wp4[i * 256 + tid];
    }
    __syncthreads();

    const int u_off = tid & 7;
    const int bp    = tid >> 3;
    const int b0 = bp * 2, b1 = b0 + 1;
    const int u  = ub * 8 + u_off;

    unsigned long long acc_if0 = 0, acc_go0 = 0, acc_if1 = 0, acc_go1 = 0;
    const float* __restrict__ h0p = h_sm + b0 * H_;
    const float* __restrict__ h1p = h_sm + b1 * H_;
    const unsigned long long* __restrict__ w2 =
        (const unsigned long long*)w_sm + u_off * 2;   // per-k stride = 16 u64

#pragma unroll 8
    for (int k = 0; k < H_; k++) {
        unsigned long long h0  = splat2(h0p[k]);
        unsigned long long h1  = splat2(h1p[k]);
        unsigned long long wif = w2[k * 16];
        unsigned long long wgo = w2[k * 16 + 1];
        fma2(acc_if0, h0, wif);
        fma2(acc_go0, h0, wgo);
        fma2(acc_if1, h1, wif);
        fma2(acc_go1, h1, wgo);
    }

    const float* __restrict__ xpd = g_xp[d];
    float* __restrict__ cptr = g_c[d];

#pragma unroll
    for (int bb = 0; bb < 2; bb++) {
        int b = bb ? b1 : b0;
        float2 vif = bb ? *(float2*)&acc_if1 : *(float2*)&acc_if0;
        float2 vgo = bb ? *(float2*)&acc_go1 : *(float2*)&acc_go0;
        size_t m = (size_t)b * S_ + t;
        float4 xp4 = *(const float4*)(xpd + m * G_ + (size_t)u * 4); // (i,f,g,o)
        float ip = xp4.x + vif.x;
        float fp = xp4.y + vif.y;
        float gp = xp4.z + vgo.x;
        float op = xp4.w + vgo.y;
        float st = sent[b * S_ + t];
        float ig = sigmoidf_(ip) * st;
        float fg = sigmoidf_(fp) * (1.0f + st);
        float og = sigmoidf_(op);
        int ci = b * H_ + u;
        float c = fg * cptr[ci] + ig * tanhf(gp);
        float h = og * tanhf(c);
        cptr[ci]   = c;
        h_next[ci] = h;
        out[m * (2 * H_) + (size_t)d * H_ + u] = h;
    }
}

// ---------------- launch ----------------
extern "C" void kernel_launch(void* const* d_in, const int* in_sizes, int n_in,
                              void* d_out, int out_size) {
    const float* x    = (const float*)d_in[0];
    const float* sent = (const float*)d_in[1];
    const float* Wi_f = (const float*)d_in[2];
    const float* bi_f = (const float*)d_in[3];
    const float* Wh_f = (const float*)d_in[4];
    const float* bh_f = (const float*)d_in[5];
    const float* Wi_b = (const float*)d_in[6];
    const float* bi_b = (const float*)d_in[7];
    const float* Wh_b = (const float*)d_in[8];
    const float* bh_b = (const float*)d_in[9];
    float* out = (float*)d_out;

    // 192 KB dynamic smem for the step kernel (idempotent; not a stream op).
    cudaFuncSetAttribute(step_kernel,
                         cudaFuncAttributeMaxDynamicSharedMemorySize, 196608);

    // state zero + Wh interleave (re-done every launch: replay-deterministic)
    prep_kernel<<<8192, 256>>>(Wh_f, Wh_b);

    // input projection for both directions
    dim3 pg(G_ / BN, M_ / BM, 2);   // (16, 256, 2)
    proj_kernel<<<pg, 256>>>(x, Wi_f, bi_f, bh_f, Wi_b, bi_b, bh_b);

    // 512 sequential LSTM steps (fwd t=s, bwd t=511-s in the same launch)
    for (int s = 0; s < S_; s++) {
        step_kernel<<<128, 256, 196608>>>(sent, out, s);
    }
}

// round 7
// speedup vs baseline: 1.2142x; 1.2142x over previous
#include <cuda_runtime.h>
#include <cuda_bf16.h>
#include <cstdint>
#include <cstddef>

#define B_ 64
#define S_ 512
#define I_ 768
#define H_ 512
#define G_ 2048            // 4*H
#define M_ 32768           // B*S
#define NBLK 128

// ---------------- device scratch (no allocations allowed) ----------------
// xp: gate-interleaved input projection [dir][m][u*4+g], g in {i,f,g,o}
__device__ __align__(16) float g_xp[2][(size_t)M_ * G_];        // 512 MB
// Wh transposed per block slice: [dir][ub][col][k], col = u_off*4+g
__device__ __align__(16) float g_wt[2][64][32][512];            // 8 MB
// hidden state ping-pong: [parity][dir][kp][b][2]  (k-pair interleaved)
__device__ __align__(16) float g_h[2][2][H_ * B_];
// grid barrier counter (monotonic within one launch; reset by prep)
__device__ unsigned int g_bar;

// ---------------- helpers ----------------
__device__ __forceinline__ unsigned long long splat2(float v) {
    unsigned long long r;
    asm("mov.b64 %0, {%1, %1};" : "=l"(r) : "f"(v));
    return r;
}
__device__ __forceinline__ void fma2(unsigned long long& acc,
                                     unsigned long long a, unsigned long long b) {
    asm("fma.rn.f32x2 %0, %1, %2, %0;" : "+l"(acc) : "l"(a), "l"(b));
}
__device__ __forceinline__ float sigmoidf_(float x) {
    return 1.0f / (1.0f + expf(-x));
}
__device__ __forceinline__ float red2(unsigned long long a) {
    float2 v = *(float2*)&a;
    return v.x + v.y;
}

// ---------------- prep: reset barrier, zero h, build transposed Wh ----------------
__global__ void prep_kernel(const float* __restrict__ Wh_f,
                            const float* __restrict__ Wh_b) {
    int idx = blockIdx.x * blockDim.x + threadIdx.x;
    if (idx < 2 * H_ * G_) {               // 2,097,152
        int d = idx >> 20;
        int r = idx & 0xFFFFF;
        int k = r >> 11;                   // 0..511
        int n = r & 2047;                  // source column: g*512 + u
        int g = n >> 9;
        int u = n & 511;
        const float* __restrict__ Wh = d ? Wh_b : Wh_f;
        g_wt[d][u >> 3][(u & 7) * 4 + g][k] = Wh[(size_t)k * G_ + n];
    }
    if (idx < 2 * 2 * H_ * B_) {           // 131072: zero both parities, both dirs
        ((float*)g_h)[idx] = 0.0f;
    }
    if (idx == 0) g_bar = 0u;
}

// ---------------- projection GEMM: xp = x @ Wi + bi + bh (both dirs) ----------------
#define BM 128
#define BN 128
#define BK 16

__global__ __launch_bounds__(256) void proj_kernel(
    const float* __restrict__ x,
    const float* __restrict__ Wi_f, const float* __restrict__ bi_f,
    const float* __restrict__ bh_f,
    const float* __restrict__ Wi_b, const float* __restrict__ bi_b,
    const float* __restrict__ bh_b)
{
    __shared__ float As[BK][BM];   // transposed: As[k][m]
    __shared__ float Bs[BK][BN];   // Bs[k][n]

    const int d  = blockIdx.z;
    const float* __restrict__ Wi = d ? Wi_b : Wi_f;
    const float* __restrict__ bi = d ? bi_b : bi_f;
    const float* __restrict__ bh = d ? bh_b : bh_f;

    const int mb = blockIdx.y;
    const int nb = blockIdx.x;
    const int tid = threadIdx.x;
    const int tx = tid & 15;
    const int ty = tid >> 4;

    unsigned long long acc[4][8];
#pragma unroll
    for (int p = 0; p < 4; p++)
#pragma unroll
        for (int c = 0; c < 8; c++) acc[p][c] = 0ULL;

    const int arow  = tid >> 2;
    const int acol4 = tid & 3;
    const float* __restrict__ xg = x + (size_t)(mb * BM) * I_;
    const float* __restrict__ wg = Wi + (size_t)(nb * BN);

    for (int kc = 0; kc < I_; kc += BK) {
#pragma unroll
        for (int j = 0; j < 2; j++) {
            int r = arow + j * 64;
            float4 v = *(const float4*)(xg + (size_t)r * I_ + kc + acol4 * 4);
            As[acol4 * 4 + 0][r] = v.x;
            As[acol4 * 4 + 1][r] = v.y;
            As[acol4 * 4 + 2][r] = v.z;
            As[acol4 * 4 + 3][r] = v.w;
        }
#pragma unroll
        for (int j = 0; j < 2; j++) {
            int idx = j * 256 + tid;
            int r = idx >> 5, c4 = idx & 31;
            float4 v = *(const float4*)(wg + (size_t)(kc + r) * G_ + c4 * 4);
            *(float4*)&Bs[r][c4 * 4] = v;
        }
        __syncthreads();

#pragma unroll
        for (int k = 0; k < BK; k++) {
            unsigned long long a[4];
#pragma unroll
            for (int p = 0; p < 4; p++)
                a[p] = *(const unsigned long long*)&As[k][ty * 8 + 2 * p];
            float4 bv0 = *(const float4*)&Bs[k][tx * 8];
            float4 bv1 = *(const float4*)&Bs[k][tx * 8 + 4];
            float bcols[8] = {bv0.x, bv0.y, bv0.z, bv0.w,
                              bv1.x, bv1.y, bv1.z, bv1.w};
#pragma unroll
            for (int c = 0; c < 8; c++) {
                unsigned long long bs = splat2(bcols[c]);
#pragma unroll
                for (int p = 0; p < 4; p++) fma2(acc[p][c], a[p], bs);
            }
        }
        __syncthreads();
    }

    float* __restrict__ xpd = g_xp[d];
    const int m0 = mb * BM + ty * 8;
    const int n0 = nb * BN + tx * 8;
#pragma unroll
    for (int c = 0; c < 8; c++) {
        int col  = n0 + c;
        float bias = bi[col] + bh[col];
        int u = col & 511;
        int g = col >> 9;
        size_t off = (size_t)(u * 4 + g);
#pragma unroll
        for (int p = 0; p < 4; p++) {
            float2 v = *(float2*)&acc[p][c];
            xpd[(size_t)(m0 + 2 * p)     * G_ + off] = v.x + bias;
            xpd[(size_t)(m0 + 2 * p + 1) * G_ + off] = v.y + bias;
        }
    }
}

// ---------------- persistent BiLSTM recurrence ----------------
// 128 CTAs (2 dirs x 64 unit-blocks of 8 units), 256 threads, 192 KB smem,
// all co-resident (1 CTA/SM). Thread = (colgroup cg: 2 units, batch b).
// k-pair f32x2: acc lanes = (k even, k odd) partial sums.
__global__ __launch_bounds__(256, 1) void lstm_persist(
    const float* __restrict__ sent, float* __restrict__ out)
{
    extern __shared__ float sm[];
    float* h_sm = sm;            // [256 kp][64 b][2] = 128 KB
    float* w_sm = sm + 32768;    // [32 col][512 k]   =  64 KB

    const int blk = blockIdx.x;
    const int d  = blk >> 6;
    const int ub = blk & 63;
    const int tid = threadIdx.x;
    const int cg = tid >> 6;     // 0..3  (units 2cg, 2cg+1 of this ub)
    const int b  = tid & 63;     // batch

    // stage Wh slice once (64 KB contiguous)
    {
        const float4* wp4 = (const float4*)&g_wt[d][ub][0][0];
        float4* ws4 = (float4*)w_sm;
#pragma unroll
        for (int i = 0; i < 16; i++) ws4[i * 256 + tid] = wp4[i * 256 + tid];
    }

    const int u0 = ub * 8 + cg * 2;          // even
    float c0 = 0.0f, c1 = 0.0f;

    const float* __restrict__ xpd = g_xp[d];
    const unsigned long long* __restrict__ wp =
        (const unsigned long long*)w_sm + (size_t)cg * 8 * 256;

    for (int s = 0; s < S_; s++) {
        const int t = d ? (S_ - 1 - s) : s;
        const int p = s & 1;
        const size_t m = (size_t)b * S_ + t;

        // prefetch xp gates (one aligned 32B chunk) + sentiment
        float4 xq0 = *(const float4*)(xpd + m * G_ + (size_t)u0 * 4);
        float4 xq1 = *(const float4*)(xpd + m * G_ + (size_t)u0 * 4 + 4);
        float st = __ldg(sent + m);

        // stage h_prev (128 KB, L2-coherent stream)
        {
            const float4* hp4 = (const float4*)g_h[p][d];
            float4* hs4 = (float4*)h_sm;
#pragma unroll 8
            for (int i = 0; i < 32; i++)
                hs4[i * 256 + tid] = __ldcg(hp4 + i * 256 + tid);
        }
        __syncthreads();

        // GEMM: 8 gate-columns x this batch, k-paired
        unsigned long long a0 = 0, a1 = 0, a2 = 0, a3 = 0;
        unsigned long long a4 = 0, a5 = 0, a6 = 0, a7 = 0;
        const unsigned long long* __restrict__ hp =
            (const unsigned long long*)h_sm + b;
#pragma unroll 8
        for (int kp = 0; kp < 256; kp++) {
            unsigned long long h2 = hp[(size_t)kp * 64];
            fma2(a0, h2, wp[kp]);
            fma2(a1, h2, wp[256  + kp]);
            fma2(a2, h2, wp[512  + kp]);
            fma2(a3, h2, wp[768  + kp]);
            fma2(a4, h2, wp[1024 + kp]);
            fma2(a5, h2, wp[1280 + kp]);
            fma2(a6, h2, wp[1536 + kp]);
            fma2(a7, h2, wp[1792 + kp]);
        }

        // gates + pointwise (unit0: a0..a3 + xq0 ; unit1: a4..a7 + xq1)
        float gi0 = red2(a0) + xq0.x;
        float gf0 = red2(a1) + xq0.y;
        float gg0 = red2(a2) + xq0.z;
        float go0 = red2(a3) + xq0.w;
        float gi1 = red2(a4) + xq1.x;
        float gf1 = red2(a5) + xq1.y;
        float gg1 = red2(a6) + xq1.z;
        float go1 = red2(a7) + xq1.w;

        float i0 = sigmoidf_(gi0) * st;
        float f0 = sigmoidf_(gf0) * (1.0f + st);
        float o0 = sigmoidf_(go0);
        c0 = f0 * c0 + i0 * tanhf(gg0);
        float h0 = o0 * tanhf(c0);

        float i1 = sigmoidf_(gi1) * st;
        float f1 = sigmoidf_(gf1) * (1.0f + st);
        float o1 = sigmoidf_(go1);
        c1 = f1 * c1 + i1 * tanhf(gg1);
        float h1 = o1 * tanhf(c1);

        // write h_next (k-pair interleaved, coalesced float2) + output
        float2 hv = make_float2(h0, h1);
        float* hn = g_h[p ^ 1][d];
        __stcg((float2*)(hn + (size_t)(u0 >> 1) * 128 + b * 2), hv);
        *(float2*)(out + m * (size_t)(2 * H_) + (size_t)d * H_ + u0) = hv;

        // grid barrier (skip after final step)
        if (s == S_ - 1) break;
        __threadfence();
        __syncthreads();
        if (tid == 0) {
            atomicAdd(&g_bar, 1u);
            const unsigned int target = (unsigned int)(s + 1) * NBLK;
            while (*((volatile unsigned int*)&g_bar) < target) { }
        }
        __syncthreads();
    }
}

// ---------------- launch ----------------
extern "C" void kernel_launch(void* const* d_in, const int* in_sizes, int n_in,
                              void* d_out, int out_size) {
    const float* x    = (const float*)d_in[0];
    const float* sent = (const float*)d_in[1];
    const float* Wi_f = (const float*)d_in[2];
    const float* bi_f = (const float*)d_in[3];
    const float* Wh_f = (const float*)d_in[4];
    const float* bh_f = (const float*)d_in[5];
    const float* Wi_b = (const float*)d_in[6];
    const float* bi_b = (const float*)d_in[7];
    const float* Wh_b = (const float*)d_in[8];
    const float* bh_b = (const float*)d_in[9];
    float* out = (float*)d_out;

    cudaFuncSetAttribute(lstm_persist,
                         cudaFuncAttributeMaxDynamicSharedMemorySize, 196608);

    // reset barrier, zero h, build transposed Wh (every launch: replay-safe)
    prep_kernel<<<8192, 256>>>(Wh_f, Wh_b);

    // input projection for both directions
    dim3 pg(G_ / BN, M_ / BM, 2);
    proj_kernel<<<pg, 256>>>(x, Wi_f, bi_f, bh_f, Wi_b, bi_b, bh_b);

    // whole recurrence in one persistent launch
    lstm_persist<<<NBLK, 256, 196608>>>(sent, out);
}

// round 9
// speedup vs baseline: 1.3502x; 1.1120x over previous
#include <cuda_runtime.h>
#include <cuda_bf16.h>
#include <cstdint>
#include <cstddef>

#define B_ 64
#define S_ 512
#define I_ 768
#define H_ 512
#define G_ 2048            // 4*H
#define M_ 32768           // B*S
#define NBLK 128

// ---------------- device scratch (no allocations allowed) ----------------
// xp: gate-interleaved input projection [dir][m][u*4+g], g in {i,f,g,o}
__device__ __align__(16) float g_xp[2][(size_t)M_ * G_];        // 512 MB
// Wh packed for the step kernel: [dir][ub][kp][u_off][8]
//   8 floats = {wi[2kp],wi[2kp+1], wf.., wg.., wo..}
__device__ __align__(16) float g_wt2[2][64][256][8][8];         // 8 MB
// hidden state ping-pong: [parity][dir] as float4[kp][bp]:
//   {h[2kp][2bp], h[2kp+1][2bp], h[2kp][2bp+1], h[2kp+1][2bp+1]}
__device__ __align__(16) float g_h[2][2][H_ * B_];
// grid barrier counter (monotonic within one launch; reset by prep)
__device__ unsigned int g_bar;

// ---------------- helpers ----------------
__device__ __forceinline__ unsigned long long splat2(float v) {
    unsigned long long r;
    asm("mov.b64 %0, {%1, %1};" : "=l"(r) : "f"(v));
    return r;
}
__device__ __forceinline__ void fma2(unsigned long long& acc,
                                     unsigned long long a, unsigned long long b) {
    asm("fma.rn.f32x2 %0, %1, %2, %0;" : "+l"(acc) : "l"(a), "l"(b));
}
__device__ __forceinline__ float sigmoidf_(float x) {
    return 1.0f / (1.0f + expf(-x));
}
__device__ __forceinline__ float red2(unsigned long long a) {
    float2 v = *(float2*)&a;
    return v.x + v.y;
}

// ---------------- prep: reset barrier, zero h, build packed Wh ----------------
__global__ void prep_kernel(const float* __restrict__ Wh_f,
                            const float* __restrict__ Wh_b) {
    int idx = blockIdx.x * blockDim.x + threadIdx.x;
    if (idx < 2 * H_ * G_) {               // 2,097,152
        int d = idx >> 20;
        int r = idx & 0xFFFFF;
        int k = r >> 11;                   // 0..511
        int n = r & 2047;                  // source column: g*512 + u
        int g = n >> 9;
        int u = n & 511;
        const float* __restrict__ Wh = d ? Wh_b : Wh_f;
        size_t dst = ((((size_t)d * 64 + (u >> 3)) * 256 + (k >> 1)) * 8
                      + (u & 7)) * 8 + (g << 1) + (k & 1);
        ((float*)g_wt2)[dst] = Wh[(size_t)k * G_ + n];
    }
    if (idx < 2 * 2 * H_ * B_) {           // zero both parities, both dirs
        ((float*)g_h)[idx] = 0.0f;
    }
    if (idx == 0) g_bar = 0u;
}

// ---------------- projection GEMM: xp = x @ Wi + bi + bh (both dirs) ----------------
#define BM 128
#define BN 128
#define BK 16

__global__ __launch_bounds__(256) void proj_kernel(
    const float* __restrict__ x,
    const float* __restrict__ Wi_f, const float* __restrict__ bi_f,
    const float* __restrict__ bh_f,
    const float* __restrict__ Wi_b, const float* __restrict__ bi_b,
    const float* __restrict__ bh_b)
{
    __shared__ float As[BK][BM];   // transposed: As[k][m]
    __shared__ float Bs[BK][BN];   // Bs[k][n]

    const int d  = blockIdx.z;
    const float* __restrict__ Wi = d ? Wi_b : Wi_f;
    const float* __restrict__ bi = d ? bi_b : bi_f;
    const float* __restrict__ bh = d ? bh_b : bh_f;

    const int mb = blockIdx.y;
    const int nb = blockIdx.x;
    const int tid = threadIdx.x;
    const int tx = tid & 15;
    const int ty = tid >> 4;

    unsigned long long acc[4][8];
#pragma unroll
    for (int p = 0; p < 4; p++)
#pragma unroll
        for (int c = 0; c < 8; c++) acc[p][c] = 0ULL;

    const int arow  = tid >> 2;
    const int acol4 = tid & 3;
    const float* __restrict__ xg = x + (size_t)(mb * BM) * I_;
    const float* __restrict__ wg = Wi + (size_t)(nb * BN);

    for (int kc = 0; kc < I_; kc += BK) {
#pragma unroll
        for (int j = 0; j < 2; j++) {
            int r = arow + j * 64;
            float4 v = *(const float4*)(xg + (size_t)r * I_ + kc + acol4 * 4);
            As[acol4 * 4 + 0][r] = v.x;
            As[acol4 * 4 + 1][r] = v.y;
            As[acol4 * 4 + 2][r] = v.z;
            As[acol4 * 4 + 3][r] = v.w;
        }
#pragma unroll
        for (int j = 0; j < 2; j++) {
            int idx = j * 256 + tid;
            int r = idx >> 5, c4 = idx & 31;
            float4 v = *(const float4*)(wg + (size_t)(kc + r) * G_ + c4 * 4);
            *(float4*)&Bs[r][c4 * 4] = v;
        }
        __syncthreads();

#pragma unroll
        for (int k = 0; k < BK; k++) {
            unsigned long long a[4];
#pragma unroll
            for (int p = 0; p < 4; p++)
                a[p] = *(const unsigned long long*)&As[k][ty * 8 + 2 * p];
            float4 bv0 = *(const float4*)&Bs[k][tx * 8];
            float4 bv1 = *(const float4*)&Bs[k][tx * 8 + 4];
            float bcols[8] = {bv0.x, bv0.y, bv0.z, bv0.w,
                              bv1.x, bv1.y, bv1.z, bv1.w};
#pragma unroll
            for (int c = 0; c < 8; c++) {
                unsigned long long bs = splat2(bcols[c]);
#pragma unroll
                for (int p = 0; p < 4; p++) fma2(acc[p][c], a[p], bs);
            }
        }
        __syncthreads();
    }

    float* __restrict__ xpd = g_xp[d];
    const int m0 = mb * BM + ty * 8;
    const int n0 = nb * BN + tx * 8;
#pragma unroll
    for (int c = 0; c < 8; c++) {
        int col  = n0 + c;
        float bias = bi[col] + bh[col];
        int u = col & 511;
        int g = col >> 9;
        size_t off = (size_t)(u * 4 + g);
#pragma unroll
        for (int p = 0; p < 4; p++) {
            float2 v = *(float2*)&acc[p][c];
            xpd[(size_t)(m0 + 2 * p)     * G_ + off] = v.x + bias;
            xpd[(size_t)(m0 + 2 * p + 1) * G_ + off] = v.y + bias;
        }
    }
}

// ---------------- persistent BiLSTM recurrence ----------------
// 128 CTAs (2 dirs x 64 unit-blocks of 8 units), 256 threads, 192 KB smem.
// Thread tile: 1 unit x 4 gates x 2 adjacent batches; k-pair f32x2 accs.
// Per k-pair per thread: 1 LDS.128 (h, both batches) + 2 LDS.128 (Wh, 4 gates)
// + 8 FFMA2  ->  fma-pipe bound (~8.2k cyc/step floor).
__global__ __launch_bounds__(256, 1) void lstm_persist(
    const float* __restrict__ sent, float* __restrict__ out)
{
    extern __shared__ float sm[];
    float* h_sm = sm;            // float4[256 kp][32 bp] = 128 KB
    float* w_sm = sm + 32768;    // float [256 kp][8 u_off][8] = 64 KB

    const int blk = blockIdx.x;
    const int d   = blk >> 6;
    const int ub  = blk & 63;
    const int tid = threadIdx.x;
    const int warp = tid >> 5, lane = tid & 31;
    const int u_off = (warp & 1) * 4 + (lane >> 3);   // 0..7
    const int bp    = (warp >> 1) * 8 + (lane & 7);   // 0..31
    const int u  = ub * 8 + u_off;
    const int b0 = bp * 2, b1 = b0 + 1;

    // stage Wh slice once (64 KB contiguous)
    {
        const float4* wp4 = (const float4*)&g_wt2[d][ub][0][0][0];
        float4* ws4 = (float4*)w_sm;
#pragma unroll
        for (int i = 0; i < 16; i++) ws4[i * 256 + tid] = wp4[i * 256 + tid];
    }

    float c0 = 0.0f, c1 = 0.0f;
    const float* __restrict__ xpd = g_xp[d];
    const ulonglong2* __restrict__ wl2 = (const ulonglong2*)w_sm + u_off * 2;
    const ulonglong2* __restrict__ hl2 = (const ulonglong2*)h_sm + bp;

    for (int s = 0; s < S_; s++) {
        const int t = d ? (S_ - 1 - s) : s;
        const int p = s & 1;

        // prefetch xp gates + sentiment (independent of h)
        float4 xq0 = __ldcs((const float4*)(xpd + ((size_t)b0 * S_ + t) * G_ + (size_t)u * 4));
        float4 xq1 = __ldcs((const float4*)(xpd + ((size_t)b1 * S_ + t) * G_ + (size_t)u * 4));
        float st0 = __ldg(sent + b0 * S_ + t);
        float st1 = __ldg(sent + b1 * S_ + t);

        // stage h_prev (128 KB, L2-coherent stream)
        {
            const float4* hp4 = (const float4*)g_h[p][d];
            float4* hs4 = (float4*)h_sm;
#pragma unroll 8
            for (int i = 0; i < 32; i++)
                hs4[i * 256 + tid] = __ldcg(hp4 + i * 256 + tid);
        }
        __syncthreads();

        // GEMM: 4 gate-columns x 2 batches, k-paired
        unsigned long long ai0 = 0, af0 = 0, ag0 = 0, ao0 = 0;
        unsigned long long ai1 = 0, af1 = 0, ag1 = 0, ao1 = 0;
#pragma unroll 8
        for (int kp = 0; kp < 256; kp++) {
            ulonglong2 h2 = hl2[(size_t)kp * 32];
            ulonglong2 wa = wl2[(size_t)kp * 16];
            ulonglong2 wb = wl2[(size_t)kp * 16 + 1];
            fma2(ai0, h2.x, wa.x);
            fma2(af0, h2.x, wa.y);
            fma2(ag0, h2.x, wb.x);
            fma2(ao0, h2.x, wb.y);
            fma2(ai1, h2.y, wa.x);
            fma2(af1, h2.y, wa.y);
            fma2(ag1, h2.y, wb.x);
            fma2(ao1, h2.y, wb.y);
        }

        // pointwise
        float gi0 = red2(ai0) + xq0.x;
        float gf0 = red2(af0) + xq0.y;
        float gg0 = red2(ag0) + xq0.z;
        float go0 = red2(ao0) + xq0.w;
        float i0 = sigmoidf_(gi0) * st0;
        float f0 = sigmoidf_(gf0) * (1.0f + st0);
        float o0 = sigmoidf_(go0);
        c0 = f0 * c0 + i0 * tanhf(gg0);
        float h0 = o0 * tanhf(c0);

        float gi1 = red2(ai1) + xq1.x;
        float gf1 = red2(af1) + xq1.y;
        float gg1 = red2(ag1) + xq1.z;
        float go1 = red2(ao1) + xq1.w;
        float i1 = sigmoidf_(gi1) * st1;
        float f1 = sigmoidf_(gf1) * (1.0f + st1);
        float o1 = sigmoidf_(go1);
        c1 = f1 * c1 + i1 * tanhf(gg1);
        float h1 = o1 * tanhf(c1);

        // write h_next in the float4[kp][bp] staging layout (L2) + output
        {
            float* hn = g_h[p ^ 1][d];
            int hbase = ((u >> 1) * 32 + bp) * 4 + (u & 1);
            __stcg(hn + hbase,     h0);
            __stcg(hn + hbase + 2, h1);
        }
        __stcs(out + ((size_t)b0 * S_ + t) * (size_t)(2 * H_) + (size_t)d * H_ + u, h0);
        __stcs(out + ((size_t)b1 * S_ + t) * (size_t)(2 * H_) + (size_t)d * H_ + u, h1);

        // grid barrier (skip after final step)
        if (s == S_ - 1) break;
        __threadfence();
        __syncthreads();
        if (tid == 0) {
            atomicAdd(&g_bar, 1u);
            const unsigned int target = (unsigned int)(s + 1) * NBLK;
            while (*((volatile unsigned int*)&g_bar) < target) { }
        }
        __syncthreads();
    }
}

// ---------------- launch ----------------
extern "C" void kernel_launch(void* const* d_in, const int* in_sizes, int n_in,
                              void* d_out, int out_size) {
    const float* x    = (const float*)d_in[0];
    const float* sent = (const float*)d_in[1];
    const float* Wi_f = (const float*)d_in[2];
    const float* bi_f = (const float*)d_in[3];
    const float* Wh_f = (const float*)d_in[4];
    const float* bh_f = (const float*)d_in[5];
    const float* Wi_b = (const float*)d_in[6];
    const float* bi_b = (const float*)d_in[7];
    const float* Wh_b = (const float*)d_in[8];
    const float* bh_b = (const float*)d_in[9];
    float* out = (float*)d_out;

    cudaFuncSetAttribute(lstm_persist,
                         cudaFuncAttributeMaxDynamicSharedMemorySize, 196608);

    // reset barrier, zero h, build packed Wh (every launch: replay-safe)
    prep_kernel<<<8192, 256>>>(Wh_f, Wh_b);

    // input projection for both directions
    dim3 pg(G_ / BN, M_ / BM, 2);
    proj_kernel<<<pg, 256>>>(x, Wi_f, bi_f, bh_f, Wi_b, bi_b, bh_b);

    // whole recurrence in one persistent launch
    lstm_persist<<<NBLK, 256, 196608>>>(sent, out);
}